// round 9
// baseline (speedup 1.0000x reference)
#include <cuda_runtime.h>
#include <math.h>

// Problem constants (PerturbationAttention): delta [B, C, D] fp32, k = 256
#define B_DIM 2048
#define C_DIM 512
#define D_DIM 256
#define K_SEL 256
#define SIG_BLOCKS 592   // 148 SMs * 4 resident blocks of 512 threads

// Scratch (no allocations allowed): sigma buffer (4 MB) + per-block maxima.
__device__ float g_sigma[B_DIM * C_DIM];
__device__ float g_blockmax[SIG_BLOCKS];

// ---------------------------------------------------------------------------
// Kernel 1: sigma[r] = ||delta[r, :]||_2 for r in [0, B*C).
// Warp-per-row, grid-stride, 4 blocks/SM resident (64 warps/SM) — measured
// best occupancy point. Each lane loads 2 float4 -> 1 KiB/warp/row, coalesced.
// ---------------------------------------------------------------------------
__global__ void __launch_bounds__(512, 4)
pa_sigma_kernel(const float* __restrict__ delta)
{
    const int lane = threadIdx.x & 31;
    const int wid  = threadIdx.x >> 5;
    const int warps_per_block = 16;
    const int gwarp = blockIdx.x * warps_per_block + wid;
    const int warp_stride = SIG_BLOCKS * warps_per_block;   // 9472

    float lmax = 0.0f;

    #pragma unroll 2
    for (int row = gwarp; row < B_DIM * C_DIM; row += warp_stride) {
        const float4* p = reinterpret_cast<const float4*>(delta + (size_t)row * D_DIM);
        float4 a = p[lane];
        float4 b = p[lane + 32];
        float s = a.x * a.x + a.y * a.y + a.z * a.z + a.w * a.w
                + b.x * b.x + b.y * b.y + b.z * b.z + b.w * b.w;

        #pragma unroll
        for (int o = 16; o > 0; o >>= 1)
            s += __shfl_xor_sync(0xffffffffu, s, o);

        float sig = sqrtf(s);
        if (lane == 0) g_sigma[row] = sig;
        lmax = fmaxf(lmax, sig);
    }

    __shared__ float smax[16];
    if (lane == 0) smax[wid] = lmax;
    __syncthreads();
    if (wid == 0) {
        float v = (lane < warps_per_block) ? smax[lane] : 0.0f;
        #pragma unroll
        for (int o = 8; o > 0; o >>= 1)
            v = fmaxf(v, __shfl_xor_sync(0xffffffffu, v, o));
        if (lane == 0) g_blockmax[blockIdx.x] = v;
    }
}

__device__ __forceinline__ float tanh_approx(float x) {
    float r;
    asm("tanh.approx.f32 %0, %1;" : "=f"(r) : "f"(x));
    return r;
}

// ---------------------------------------------------------------------------
// Kernel 2: one batch row per block (512 threads = 512 columns).
//   t = tanh(1 - sigma/gmax); att = softmax_C(t); zero K_SEL smallest att
//   (ties -> lowest index). Radix select on float bits, with:
//   - REDUX warp reductions (t >= 0, bit order == value order)
//   - warp-aggregated histogram atomics
//   - dead-pass skip via bit-exact kmin/kmax (shared leading bytes)
//   - 4 __syncthreads per radix pass
// ---------------------------------------------------------------------------
__global__ void __launch_bounds__(512)
pa_select_kernel(float* __restrict__ out)
{
    const int b    = blockIdx.x;
    const int i    = threadIdx.x;       // column 0..511
    const int lane = i & 31;
    const int w    = i >> 5;            // warp 0..15

    __shared__ unsigned s_max[16], s_min[16];
    __shared__ float    s_sum[16];
    __shared__ unsigned s_hist[256];
    __shared__ unsigned s_wsum[8];
    __shared__ unsigned s_bin, s_excl;
    __shared__ int      s_wcnt[16];

    // ---- global max over per-block maxima (all values >= 0) ----
    {
        float v = (i < SIG_BLOCKS) ? g_blockmax[i] : 0.0f;
        if (i + 512 < SIG_BLOCKS) v = fmaxf(v, g_blockmax[i + 512]);
        unsigned vb = __reduce_max_sync(0xffffffffu, __float_as_uint(v));
        if (lane == 0) s_max[w] = vb;
    }
    __syncthreads();
    unsigned gb = s_max[0];
    #pragma unroll
    for (int j = 1; j < 16; j++) gb = max(gb, s_max[j]);
    const float gmax = __uint_as_float(gb);
    __syncthreads();                      // s_max reused below

    const float sig = g_sigma[b * C_DIM + i];
    const float t   = tanh_approx(1.0f - sig / gmax);   // t in [0, tanh(1)]

    // ---- block max AND min of t (REDUX on bits; t >= 0) ----
    {
        const unsigned tb = __float_as_uint(t);
        unsigned wmax = __reduce_max_sync(0xffffffffu, tb);
        unsigned wmin = __reduce_min_sync(0xffffffffu, tb);
        if (lane == 0) { s_max[w] = wmax; s_min[w] = wmin; }
    }
    __syncthreads();
    unsigned mb = s_max[0], nbits = s_min[0];
    #pragma unroll
    for (int j = 1; j < 16; j++) {
        mb    = max(mb, s_max[j]);
        nbits = min(nbits, s_min[j]);
    }
    const float m = __uint_as_float(mb);     // t_max
    const float n = __uint_as_float(nbits);  // t_min

    const float e = __expf(t - m);

    // ---- block sum of e ----
    float s = e;
    #pragma unroll
    for (int o = 16; o > 0; o >>= 1)
        s += __shfl_xor_sync(0xffffffffu, s, o);
    if (lane == 0) s_sum[w] = s;
    __syncthreads();
    s = s_sum[0];
    #pragma unroll
    for (int j = 1; j < 16; j++) s += s_sum[j];

    const float att = e / s;
    const unsigned key = __float_as_uint(att);   // att > 0: bit order == value order

    // ---- bit-exact key bounds (max-t thread computes __expf(0)=1 exactly) ----
    const unsigned kmin = __float_as_uint(__expf(n - m) / s);
    const unsigned kmax = __float_as_uint(1.0f / s);

    // shared leading bytes -> skip dead radix passes (cap 3 => at least 1 pass)
    const int nb = min(3, __clz(kmin ^ kmax) >> 3);
    const int start_shift = 24 - 8 * nb;

    unsigned prefix = (nb == 0) ? 0u : (kmin >> (start_shift + 8));
    unsigned krem   = K_SEL;     // 1-based rank remaining within current bucket

    for (int shift = start_shift; shift >= 0; shift -= 8) {
        if (i < 256) s_hist[i] = 0u;
        __syncthreads();

        const bool in_bucket = (shift == 24) || ((key >> (shift + 8)) == prefix);
        // warp-aggregated histogram (clustered digits -> 1 atomic per group)
        {
            unsigned digit = in_bucket ? ((key >> shift) & 255u) : 256u;
            unsigned grp   = __match_any_sync(0xffffffffu, digit);
            if (in_bucket && lane == (__ffs(grp) - 1u))
                atomicAdd(&s_hist[digit], (unsigned)__popc(grp));
        }
        __syncthreads();

        // inclusive scan over 256 bins (warps 0-7) + cross-warp offsets
        unsigned h = 0u, incl = 0u;
        if (i < 256) {
            h = s_hist[i];
            unsigned x = h;
            #pragma unroll
            for (int o = 1; o < 32; o <<= 1) {
                unsigned y = __shfl_up_sync(0xffffffffu, x, o);
                if (lane >= o) x += y;
            }
            if (lane == 31) s_wsum[w] = x;
            incl = x;
        }
        __syncthreads();
        if (i < 256) {
            unsigned off = 0u;
            #pragma unroll
            for (int j = 0; j < 8; j++)
                if (j < w) off += s_wsum[j];
            incl += off;
            unsigned excl = incl - h;
            if (incl >= krem && excl < krem) { s_bin = (unsigned)i; s_excl = excl; }
        }
        __syncthreads();

        prefix = (prefix << 8) | s_bin;
        krem  -= s_excl;
        // next write to s_bin/s_excl is 3 syncs away; s_hist clear is behind
        // the first sync of the next pass — no trailing sync needed
    }

    const unsigned T = prefix;          // exact bits of the k-th smallest att
    const unsigned tie_budget = krem;   // #values == T to zero (lowest idx first)

    // ---- tie rank: index-ordered prefix count of (key == T) ----
    const bool eq = (key == T);
    const unsigned bal = __ballot_sync(0xffffffffu, eq);
    if (lane == 0) s_wcnt[w] = __popc(bal);
    __syncthreads();
    int woff = 0;
    #pragma unroll
    for (int j = 0; j < 16; j++)
        if (j < w) woff += s_wcnt[j];
    const unsigned tie_rank = (unsigned)woff + (unsigned)__popc(bal & ((1u << lane) - 1u));

    const bool zero = (key < T) || (eq && tie_rank < tie_budget);
    out[b * C_DIM + i] = zero ? 0.0f : att;
}

// ---------------------------------------------------------------------------
// Launch: two kernels, graph-capturable, allocation-free.
// ---------------------------------------------------------------------------
extern "C" void kernel_launch(void* const* d_in, const int* in_sizes, int n_in,
                              void* d_out, int out_size)
{
    const float* delta = (const float*)d_in[0];
    float* out = (float*)d_out;
    (void)in_sizes; (void)n_in; (void)out_size;

    pa_sigma_kernel<<<SIG_BLOCKS, 512>>>(delta);
    pa_select_kernel<<<B_DIM, C_DIM>>>(out);
}

// round 11
// speedup vs baseline: 1.0103x; 1.0103x over previous
#include <cuda_runtime.h>
#include <math.h>

// Problem constants (PerturbationAttention): delta [B, C, D] fp32, k = 256
#define B_DIM 2048
#define C_DIM 512
#define D_DIM 256
#define K_SEL 256
#define SIG_BLOCKS 592   // 148 SMs * 4 resident blocks of 512 threads

// Scratch (no allocations allowed): sigma buffer (4 MB) + per-block maxima.
__device__ float g_sigma[B_DIM * C_DIM];
__device__ float g_blockmax[SIG_BLOCKS];

// ---------------------------------------------------------------------------
// Kernel 1: sigma[r] = ||delta[r, :]||_2 for r in [0, B*C).
// Warp-per-row, grid-stride, 4 blocks/SM resident (64 warps/SM) — measured
// best occupancy point, ~87% of HBM spec. Unchanged from R5.
// ---------------------------------------------------------------------------
__global__ void __launch_bounds__(512, 4)
pa_sigma_kernel(const float* __restrict__ delta)
{
    const int lane = threadIdx.x & 31;
    const int wid  = threadIdx.x >> 5;
    const int warps_per_block = 16;
    const int gwarp = blockIdx.x * warps_per_block + wid;
    const int warp_stride = SIG_BLOCKS * warps_per_block;   // 9472

    float lmax = 0.0f;

    #pragma unroll 2
    for (int row = gwarp; row < B_DIM * C_DIM; row += warp_stride) {
        const float4* p = reinterpret_cast<const float4*>(delta + (size_t)row * D_DIM);
        float4 a = p[lane];
        float4 b = p[lane + 32];
        float s = a.x * a.x + a.y * a.y + a.z * a.z + a.w * a.w
                + b.x * b.x + b.y * b.y + b.z * b.z + b.w * b.w;

        #pragma unroll
        for (int o = 16; o > 0; o >>= 1)
            s += __shfl_xor_sync(0xffffffffu, s, o);

        float sig = sqrtf(s);
        if (lane == 0) g_sigma[row] = sig;
        lmax = fmaxf(lmax, sig);
    }

    __shared__ float smax[16];
    if (lane == 0) smax[wid] = lmax;
    __syncthreads();
    if (wid == 0) {
        float v = (lane < warps_per_block) ? smax[lane] : 0.0f;
        #pragma unroll
        for (int o = 8; o > 0; o >>= 1)
            v = fmaxf(v, __shfl_xor_sync(0xffffffffu, v, o));
        if (lane == 0) g_blockmax[blockIdx.x] = v;
    }
}

__device__ __forceinline__ float tanh_approx(float x) {
    float r;
    asm("tanh.approx.f32 %0, %1;" : "=f"(r) : "f"(x));
    return r;
}

// ---------------------------------------------------------------------------
// Kernel 2: one batch row per block (512 threads = 512 columns).
//   t = tanh(1 - sigma/gmax); att = softmax_C(t); zero K_SEL smallest att
//   (ties -> lowest index). Radix select on float bits.
// __launch_bounds__(512, 4) caps regs at 32 -> 4 resident blocks/SM (the RF
// is exactly 512*32*4); occupancy is the measured dominant lever
// (occ 90% -> 21.7us at 30 regs vs occ 67% -> ~26us at 34-36 regs).
// Shuffle-based reductions (R5 shape) + dead-pass skip via bit-exact key
// bounds (keys share leading bytes; skip those radix passes entirely).
// ---------------------------------------------------------------------------
__global__ void __launch_bounds__(512, 4)
pa_select_kernel(float* __restrict__ out)
{
    const int b    = blockIdx.x;
    const int i    = threadIdx.x;       // column 0..511
    const int lane = i & 31;
    const int w    = i >> 5;            // warp 0..15

    __shared__ float    s_red[16];
    __shared__ float    s_red2[16];
    __shared__ unsigned s_hist[256];
    __shared__ unsigned s_wsum[8];
    __shared__ unsigned s_bin, s_excl;
    __shared__ int      s_wcnt[16];

    // ---- global max over per-block maxima (L2-resident) ----
    {
        float v = (i < SIG_BLOCKS) ? g_blockmax[i] : 0.0f;
        if (i + 512 < SIG_BLOCKS) v = fmaxf(v, g_blockmax[i + 512]);
        #pragma unroll
        for (int o = 16; o > 0; o >>= 1)
            v = fmaxf(v, __shfl_xor_sync(0xffffffffu, v, o));
        if (lane == 0) s_red[w] = v;
    }
    __syncthreads();
    float gmax = s_red[0];
    #pragma unroll
    for (int j = 1; j < 16; j++) gmax = fmaxf(gmax, s_red[j]);
    __syncthreads();                      // s_red reused below

    const float sig = g_sigma[b * C_DIM + i];
    const float t   = tanh_approx(1.0f - sig / gmax);   // t in [0, tanh(1)]

    // ---- block max AND min of t (shuffle, both in one stage) ----
    float m = t, n = t;
    #pragma unroll
    for (int o = 16; o > 0; o >>= 1) {
        m = fmaxf(m, __shfl_xor_sync(0xffffffffu, m, o));
        n = fminf(n, __shfl_xor_sync(0xffffffffu, n, o));
    }
    if (lane == 0) { s_red[w] = m; s_red2[w] = n; }
    __syncthreads();
    {
        float vm = s_red[lane & 15];
        float vn = s_red2[lane & 15];
        #pragma unroll
        for (int o = 8; o > 0; o >>= 1) {
            vm = fmaxf(vm, __shfl_xor_sync(0xffffffffu, vm, o));
            vn = fminf(vn, __shfl_xor_sync(0xffffffffu, vn, o));
        }
        m = vm; n = vn;   // every thread has block max/min
    }
    __syncthreads();

    const float e = __expf(t - m);

    // ---- block sum of e ----
    float s = e;
    #pragma unroll
    for (int o = 16; o > 0; o >>= 1)
        s += __shfl_xor_sync(0xffffffffu, s, o);
    if (lane == 0) s_red[w] = s;
    __syncthreads();
    {
        float v = s_red[lane & 15];
        #pragma unroll
        for (int o = 8; o > 0; o >>= 1)
            v += __shfl_xor_sync(0xffffffffu, v, o);
        s = v;
    }

    const float att = e / s;
    const unsigned key = __float_as_uint(att);   // att > 0: bit order == value order

    // ---- bit-exact key bounds (max-t thread computes __expf(0)=1 exactly;
    //      min-t thread computes __expf(n-m)/s — identical expressions) ----
    const unsigned kmin = __float_as_uint(__expf(n - m) / s);
    const unsigned kmax = __float_as_uint(1.0f / s);

    // shared leading bytes -> skip dead radix passes (cap 3 => at least 1 pass)
    const int nb = min(3, __clz(kmin ^ kmax) >> 3);
    const int start_shift = 24 - 8 * nb;

    unsigned prefix = (nb == 0) ? 0u : (kmin >> (start_shift + 8));
    unsigned krem   = K_SEL;     // 1-based rank remaining within current bucket

    for (int shift = start_shift; shift >= 0; shift -= 8) {
        if (i < 256) s_hist[i] = 0u;
        __syncthreads();

        const bool in_bucket = (shift == 24) || ((key >> (shift + 8)) == prefix);
        // warp-aggregated histogram (clustered digits -> 1 atomic per group)
        {
            unsigned digit = in_bucket ? ((key >> shift) & 255u) : 256u;
            unsigned grp   = __match_any_sync(0xffffffffu, digit);
            if (in_bucket && lane == (__ffs(grp) - 1u))
                atomicAdd(&s_hist[digit], (unsigned)__popc(grp));
        }
        __syncthreads();

        // inclusive scan over 256 bins (warps 0-7) + cross-warp offsets
        unsigned h = 0u, incl = 0u;
        if (i < 256) {
            h = s_hist[i];
            unsigned x = h;
            #pragma unroll
            for (int o = 1; o < 32; o <<= 1) {
                unsigned y = __shfl_up_sync(0xffffffffu, x, o);
                if (lane >= o) x += y;
            }
            if (lane == 31) s_wsum[w] = x;
            incl = x;
        }
        __syncthreads();
        if (i < 256) {
            unsigned off = 0u;
            #pragma unroll
            for (int j = 0; j < 8; j++)
                if (j < w) off += s_wsum[j];
            incl += off;
            unsigned excl = incl - h;
            if (incl >= krem && excl < krem) { s_bin = (unsigned)i; s_excl = excl; }
        }
        __syncthreads();

        prefix = (prefix << 8) | s_bin;
        krem  -= s_excl;
        // next write to s_bin/s_excl is 3 syncs away — no trailing sync needed
    }

    const unsigned T = prefix;          // exact bits of the k-th smallest att
    const unsigned tie_budget = krem;   // #values == T to zero (lowest idx first)

    // ---- tie rank: index-ordered prefix count of (key == T) ----
    const bool eq = (key == T);
    const unsigned bal = __ballot_sync(0xffffffffu, eq);
    if (lane == 0) s_wcnt[w] = __popc(bal);
    __syncthreads();
    int woff = 0;
    #pragma unroll
    for (int j = 0; j < 16; j++)
        if (j < w) woff += s_wcnt[j];
    const unsigned tie_rank = (unsigned)woff + (unsigned)__popc(bal & ((1u << lane) - 1u));

    const bool zero = (key < T) || (eq && tie_rank < tie_budget);
    out[b * C_DIM + i] = zero ? 0.0f : att;
}

// ---------------------------------------------------------------------------
// Launch: two kernels, graph-capturable, allocation-free.
// ---------------------------------------------------------------------------
extern "C" void kernel_launch(void* const* d_in, const int* in_sizes, int n_in,
                              void* d_out, int out_size)
{
    const float* delta = (const float*)d_in[0];
    float* out = (float*)d_out;
    (void)in_sizes; (void)n_in; (void)out_size;

    pa_sigma_kernel<<<SIG_BLOCKS, 512>>>(delta);
    pa_select_kernel<<<B_DIM, C_DIM>>>(out);
}

// round 13
// speedup vs baseline: 1.0447x; 1.0341x over previous
#include <cuda_runtime.h>
#include <math.h>

// Problem constants (PerturbationAttention): delta [B, C, D] fp32, k = 256
#define B_DIM 2048
#define C_DIM 512
#define D_DIM 256
#define K_SEL 256
#define SIG_BLOCKS 592   // 148 SMs * 4 resident blocks of 512 threads

// Scratch (no allocations allowed): sigma buffer (4 MB) + per-block maxima.
__device__ float g_sigma[B_DIM * C_DIM];
__device__ float g_blockmax[SIG_BLOCKS];

// ---------------------------------------------------------------------------
// Kernel 1: sigma[r] = ||delta[r, :]||_2 for r in [0, B*C).
// Warp-per-row, grid-stride, 4 blocks/SM resident — measured at the
// ~7.1 TB/s LTS/HBM ceiling. __ldcs: pure stream, evict-first.
// ---------------------------------------------------------------------------
__global__ void __launch_bounds__(512, 4)
pa_sigma_kernel(const float* __restrict__ delta)
{
    const int lane = threadIdx.x & 31;
    const int wid  = threadIdx.x >> 5;
    const int warps_per_block = 16;
    const int gwarp = blockIdx.x * warps_per_block + wid;
    const int warp_stride = SIG_BLOCKS * warps_per_block;   // 9472

    float lmax = 0.0f;

    #pragma unroll 2
    for (int row = gwarp; row < B_DIM * C_DIM; row += warp_stride) {
        const float4* p = reinterpret_cast<const float4*>(delta + (size_t)row * D_DIM);
        float4 a = __ldcs(p + lane);
        float4 b = __ldcs(p + lane + 32);
        float s = a.x * a.x + a.y * a.y + a.z * a.z + a.w * a.w
                + b.x * b.x + b.y * b.y + b.z * b.z + b.w * b.w;

        #pragma unroll
        for (int o = 16; o > 0; o >>= 1)
            s += __shfl_xor_sync(0xffffffffu, s, o);

        float sig = sqrtf(s);
        if (lane == 0) g_sigma[row] = sig;
        lmax = fmaxf(lmax, sig);
    }

    __shared__ float smax[16];
    if (lane == 0) smax[wid] = lmax;
    __syncthreads();
    if (wid == 0) {
        float v = (lane < warps_per_block) ? smax[lane] : 0.0f;
        #pragma unroll
        for (int o = 8; o > 0; o >>= 1)
            v = fmaxf(v, __shfl_xor_sync(0xffffffffu, v, o));
        if (lane == 0) g_blockmax[blockIdx.x] = v;
    }
}

__device__ __forceinline__ float tanh_approx(float x) {
    float r;
    asm("tanh.approx.f32 %0, %1;" : "=f"(r) : "f"(x));
    return r;
}

// ---------------------------------------------------------------------------
// Kernel 2: one batch row per block (512 threads = 512 columns).
//   t = tanh(1 - sigma/gmax); att = softmax_C(t); zero K_SEL smallest att
//   (ties -> lowest index). Radix select on float bits.
// NUMERICS ARE LOAD-BEARING: keep `sig/gmax` and `e/s` exactly as written —
// the k-boundary gap is sub-ulp (R12: FFMA-contracted recip forms flipped one
// selection -> rel_err 1.9e-3). These exact forms passed 5 rounds at 3.9e-7.
// __launch_bounds__(512, 4) caps regs at 32 -> 4 resident blocks/SM
// (RF = 512*32*4 exactly); occ ~89% measured, select at its MUFU floor.
// ---------------------------------------------------------------------------
__global__ void __launch_bounds__(512, 4)
pa_select_kernel(float* __restrict__ out)
{
    const int b    = blockIdx.x;
    const int i    = threadIdx.x;       // column 0..511
    const int lane = i & 31;
    const int w    = i >> 5;            // warp 0..15

    __shared__ float    s_red[16];
    __shared__ unsigned s_hist[256];
    __shared__ unsigned s_wsum[8];
    __shared__ unsigned s_bin, s_excl;
    __shared__ int      s_wcnt[16];

    // ---- global max over per-block maxima (L2-resident) ----
    {
        float v = (i < SIG_BLOCKS) ? g_blockmax[i] : 0.0f;
        if (i + 512 < SIG_BLOCKS) v = fmaxf(v, g_blockmax[i + 512]);
        #pragma unroll
        for (int o = 16; o > 0; o >>= 1)
            v = fmaxf(v, __shfl_xor_sync(0xffffffffu, v, o));
        if (lane == 0) s_red[w] = v;
    }
    __syncthreads();
    float gmax = s_red[0];
    #pragma unroll
    for (int j = 1; j < 16; j++) gmax = fmaxf(gmax, s_red[j]);
    __syncthreads();                      // s_red reused below

    const float sig = g_sigma[b * C_DIM + i];
    const float t   = tanh_approx(1.0f - sig / gmax);   // t in [0, tanh(1)]

    // ---- block max of t (softmax stabilization) ----
    float m = t;
    #pragma unroll
    for (int o = 16; o > 0; o >>= 1)
        m = fmaxf(m, __shfl_xor_sync(0xffffffffu, m, o));
    if (lane == 0) s_red[w] = m;
    __syncthreads();
    {
        float vm = s_red[lane & 15];
        #pragma unroll
        for (int o = 8; o > 0; o >>= 1)
            vm = fmaxf(vm, __shfl_xor_sync(0xffffffffu, vm, o));
        m = vm;   // every thread has the block max
    }
    __syncthreads();

    const float e = __expf(t - m);

    // ---- block sum of e ----
    float s = e;
    #pragma unroll
    for (int o = 16; o > 0; o >>= 1)
        s += __shfl_xor_sync(0xffffffffu, s, o);
    if (lane == 0) s_red[w] = s;
    __syncthreads();
    {
        float v = s_red[lane & 15];
        #pragma unroll
        for (int o = 8; o > 0; o >>= 1)
            v += __shfl_xor_sync(0xffffffffu, v, o);
        s = v;
    }

    const float att = e / s;
    const unsigned key = __float_as_uint(att);   // att > 0: bit order == value order

    // ---- radix select: find k-th smallest key (fixed 4 passes, unrolled) ----
    unsigned prefix = 0u;
    unsigned krem   = K_SEL;     // 1-based rank remaining within current bucket

    #pragma unroll
    for (int shift = 24; shift >= 0; shift -= 8) {
        if (i < 256) s_hist[i] = 0u;
        __syncthreads();

        const bool in_bucket = (shift == 24) || ((key >> (shift + 8)) == prefix);
        // warp-aggregated histogram (clustered digits -> 1 atomic per group)
        {
            unsigned digit = in_bucket ? ((key >> shift) & 255u) : 256u;
            unsigned grp   = __match_any_sync(0xffffffffu, digit);
            if (in_bucket && lane == (__ffs(grp) - 1u))
                atomicAdd(&s_hist[digit], (unsigned)__popc(grp));
        }
        __syncthreads();

        // inclusive scan over 256 bins (warps 0-7) + cross-warp offsets
        unsigned h = 0u, incl = 0u;
        if (i < 256) {
            h = s_hist[i];
            unsigned x = h;
            #pragma unroll
            for (int o = 1; o < 32; o <<= 1) {
                unsigned y = __shfl_up_sync(0xffffffffu, x, o);
                if (lane >= o) x += y;
            }
            if (lane == 31) s_wsum[w] = x;
            incl = x;
        }
        __syncthreads();
        if (i < 256) {
            unsigned off = 0u;
            #pragma unroll
            for (int j = 0; j < 8; j++)
                if (j < w) off += s_wsum[j];
            incl += off;
            unsigned excl = incl - h;
            if (incl >= krem && excl < krem) { s_bin = (unsigned)i; s_excl = excl; }
        }
        __syncthreads();

        prefix = (prefix << 8) | s_bin;
        krem  -= s_excl;
        // next write to s_bin/s_excl is 3 syncs away — no trailing sync needed
    }

    const unsigned T = prefix;          // exact bits of the k-th smallest att
    const unsigned tie_budget = krem;   // #values == T to zero (lowest idx first)

    // ---- tie rank: index-ordered prefix count of (key == T) ----
    const bool eq = (key == T);
    const unsigned bal = __ballot_sync(0xffffffffu, eq);
    if (lane == 0) s_wcnt[w] = __popc(bal);
    __syncthreads();
    int woff = 0;
    #pragma unroll
    for (int j = 0; j < 16; j++)
        if (j < w) woff += s_wcnt[j];
    const unsigned tie_rank = (unsigned)woff + (unsigned)__popc(bal & ((1u << lane) - 1u));

    const bool zero = (key < T) || (eq && tie_rank < tie_budget);
    out[b * C_DIM + i] = zero ? 0.0f : att;
}

// ---------------------------------------------------------------------------
// Launch: two kernels, graph-capturable, allocation-free.
// ---------------------------------------------------------------------------
extern "C" void kernel_launch(void* const* d_in, const int* in_sizes, int n_in,
                              void* d_out, int out_size)
{
    const float* delta = (const float*)d_in[0];
    float* out = (float*)d_out;
    (void)in_sizes; (void)n_in; (void)out_size;

    pa_sigma_kernel<<<SIG_BLOCKS, 512>>>(delta);
    pa_select_kernel<<<B_DIM, C_DIM>>>(out);
}